// round 5
// baseline (speedup 1.0000x reference)
#include <cuda_runtime.h>
#include <math.h>
#include <stdint.h>

#define B_ 4
#define T_ 2048
#define C_ 768
#define H_ 16
#define D_ 48

// ---------------- scratch (static device globals; no allocation) ----------------
__device__ float g_qh[B_*H_*T_*D_];   // Q, roped, [B,H,T,D]
__device__ float g_kh[B_*H_*T_*D_];   // K, roped, [B,H,T,D]
__device__ float g_vh[B_*H_*T_*D_];   // V,        [B,H,T,D]
__device__ float g_ctx[B_*T_*C_];     // attention output, [B,T,C]
__device__ float g_cos[T_*D_];
__device__ float g_sin[T_*D_];

// ---------------- helpers -------------------------------------------------------
__device__ __forceinline__ float to_tf32(float x) {
    uint32_t u;
    asm("cvt.rna.tf32.f32 %0, %1;" : "=r"(u) : "f"(x));
    return __uint_as_float(u);
}

// d += a * b   (m16n8k8, tf32 inputs as f32 bit patterns, f32 accum)
__device__ __forceinline__ void mma_tf32(float* d, const float* a, const float* b) {
    asm volatile(
        "mma.sync.aligned.m16n8k8.row.col.f32.tf32.tf32.f32 "
        "{%0,%1,%2,%3}, {%4,%5,%6,%7}, {%8,%9}, {%0,%1,%2,%3};\n"
        : "+f"(d[0]), "+f"(d[1]), "+f"(d[2]), "+f"(d[3])
        : "r"(__float_as_uint(a[0])), "r"(__float_as_uint(a[1])),
          "r"(__float_as_uint(a[2])), "r"(__float_as_uint(a[3])),
          "r"(__float_as_uint(b[0])), "r"(__float_as_uint(b[1])));
}

// column-pair permutation within an 8-col k-group: col c -> 2*(c&3) + ((c&4)>>2)
// so fragment pair (tg, tg+4) is the contiguous float2 at offset 2*tg.
__device__ __forceinline__ int pbase4(int c4) {        // c4 multiple of 4
    return (c4 & ~7) | ((c4 >> 2) & 1);                // store at pbase + 2*j
}

// ---------------- RoPE table (fp64 for accuracy) --------------------------------
__global__ void rope_table_kernel() {
    int i = blockIdx.x * blockDim.x + threadIdx.x;
    if (i >= T_ * D_) return;
    int t = i / D_, d = i % D_;
    int p = (d < D_/2) ? d : d - D_/2;
    double inv = exp(-(2.0 * p / (double)D_) * log(10000.0));
    double ang = (double)t * inv;
    g_cos[i] = (float)cos(ang);
    g_sin[i] = (float)sin(ang);
}

// ---------------- fused QKV projection + bias + RoPE (tf32 mma) -----------------
// grid: (BT/64, H, 3)  block: 128 (4 warps). Tile: 64 x 48 (one head), K-chunk 32.
// smem pitch 40 floats (pitch/2 = 20 ≡ 4 mod 8 -> conflict-free float2 frags).
__global__ __launch_bounds__(128) void qkv_proj_kernel(
    const float* __restrict__ X,
    const float* __restrict__ Wq, const float* __restrict__ bq,
    const float* __restrict__ Wk, const float* __restrict__ bk,
    const float* __restrict__ Wv, const float* __restrict__ bv)
{
    const int mt = blockIdx.x, h = blockIdx.y, which = blockIdx.z;
    const float* W    = (which == 0) ? Wq : ((which == 1) ? Wk : Wv);
    const float* bias = (which == 0) ? bq : ((which == 1) ? bk : bv);
    float* out        = (which == 0) ? g_qh : ((which == 1) ? g_kh : g_vh);

    __shared__ float As[64][40];   // X tile, pair-permuted k columns
    __shared__ float Bs[48][40];   // W tile, pair-permuted k columns

    const int tid  = threadIdx.x;
    const int lane = tid & 31;
    const int w    = tid >> 5;
    const int row0 = mt * 64, col0 = h * 48;
    const int g    = lane >> 2;
    const int tg   = lane & 3;

    float acc[6][4] = {};

    for (int k0 = 0; k0 < C_; k0 += 32) {
        #pragma unroll
        for (int i = 0; i < 4; i++) {              // 64x32 = 512 float4
            int idx = tid + i * 128;
            int r = idx >> 3, c4 = (idx & 7) * 4;
            float4 v = *(const float4*)&X[(size_t)(row0 + r) * C_ + k0 + c4];
            int pb = pbase4(c4);
            As[r][pb+0] = to_tf32(v.x); As[r][pb+2] = to_tf32(v.y);
            As[r][pb+4] = to_tf32(v.z); As[r][pb+6] = to_tf32(v.w);
        }
        #pragma unroll
        for (int i = 0; i < 3; i++) {              // 48x32 = 384 float4
            int idx = tid + i * 128;
            int r = idx >> 3, c4 = (idx & 7) * 4;
            float4 v = *(const float4*)&W[(size_t)(col0 + r) * C_ + k0 + c4];
            int pb = pbase4(c4);
            Bs[r][pb+0] = to_tf32(v.x); Bs[r][pb+2] = to_tf32(v.y);
            Bs[r][pb+4] = to_tf32(v.z); Bs[r][pb+6] = to_tf32(v.w);
        }
        __syncthreads();
        #pragma unroll
        for (int ks = 0; ks < 4; ks++) {
            const int ko = ks * 8 + 2 * tg;
            float2 a0 = *(const float2*)&As[w*16 + g    ][ko];
            float2 a1 = *(const float2*)&As[w*16 + g + 8][ko];
            float a[4] = {a0.x, a1.x, a0.y, a1.y};
            #pragma unroll
            for (int nf = 0; nf < 6; nf++) {
                float2 bb = *(const float2*)&Bs[nf*8 + g][ko];
                mma_tf32(acc[nf], a, &bb.x);
            }
        }
        __syncthreads();
    }

    // epilogue: bias + RoPE fully in registers (pair d <-> d+24 == frag nf <-> nf+3)
    #pragma unroll
    for (int half = 0; half < 2; half++) {
        int grow = row0 + w * 16 + g + half * 8;
        int b = grow >> 11;             // T_ = 2048
        int t = grow & (T_ - 1);
        size_t base = ((size_t)((b * H_ + h) * T_) + t) * D_;
        if (which == 2) {
            #pragma unroll
            for (int nf = 0; nf < 6; nf++) {
                int d = nf * 8 + 2 * tg;
                float2 v;
                v.x = acc[nf][2*half+0] + bias[col0 + d];
                v.y = acc[nf][2*half+1] + bias[col0 + d + 1];
                *(float2*)&out[base + d] = v;
            }
        } else {
            #pragma unroll
            for (int nf = 0; nf < 3; nf++) {
                int d = nf * 8 + 2 * tg;
                float c0 = g_cos[t * D_ + d],     s0 = g_sin[t * D_ + d];
                float c1 = g_cos[t * D_ + d + 1], s1 = g_sin[t * D_ + d + 1];
                float x1a = acc[nf  ][2*half+0] + bias[col0 + d];
                float x1b = acc[nf  ][2*half+1] + bias[col0 + d + 1];
                float x2a = acc[nf+3][2*half+0] + bias[col0 + d + 24];
                float x2b = acc[nf+3][2*half+1] + bias[col0 + d + 25];
                float2 lo, hi;
                lo.x = x1a * c0 - x2a * s0;  lo.y = x1b * c1 - x2b * s1;
                hi.x = x2a * c0 + x1a * s0;  hi.y = x2b * c1 + x1b * s1;
                *(float2*)&out[base + d]      = lo;
                *(float2*)&out[base + d + 24] = hi;
            }
        }
    }
}

// ---------------- flash-style causal attention (tf32 mma) -----------------------
// grid: (T/64, B*H)  block: 128 (4 warps). S tile 64x64, D=48 resident.
// Qs/KP pitch 56 (pitch2=28 ≡ 4 mod 8), Vt pitch 72 (pitch2=36 ≡ 4 mod 8).
// P never touches smem: PV A-fragments rebuilt from registers via shuffles.
__global__ __launch_bounds__(128) void attn_kernel(const float* __restrict__ amask)
{
    const int qi = gridDim.x - 1 - blockIdx.x;
    const int bh = blockIdx.y;
    const int b = bh >> 4;
    const float* Q = g_qh + (size_t)bh * T_ * D_;
    const float* K = g_kh + (size_t)bh * T_ * D_;
    const float* V = g_vh + (size_t)bh * T_ * D_;

    __shared__ float Qs[64][56];   // Q tile, pair-permuted d columns
    __shared__ float KP[64][56];   // K tile, pair-permuted d columns
    __shared__ float Vt[48][72];   // V transposed [d][key], pair-permuted key cols
    __shared__ float Ms[64];       // additive padding mask for current key block

    const int tid  = threadIdx.x;
    const int lane = tid & 31;
    const int w    = tid >> 5;
    const int g    = lane >> 2;
    const int tg   = lane & 3;
    const unsigned FULL = 0xffffffffu;

    #pragma unroll
    for (int i = 0; i < 6; i++) {            // 64x48 = 768 float4
        int idx = tid + i * 128;
        int r = idx / 12, c4 = (idx % 12) * 4;
        float4 v = *(const float4*)&Q[(size_t)(qi * 64 + r) * D_ + c4];
        int pb = pbase4(c4);
        Qs[r][pb+0] = to_tf32(v.x); Qs[r][pb+2] = to_tf32(v.y);
        Qs[r][pb+4] = to_tf32(v.z); Qs[r][pb+6] = to_tf32(v.w);
    }

    float m_i[2], l_i[2] = {0.f, 0.f};
    m_i[0] = -INFINITY; m_i[1] = -INFINITY;
    float o[6][4] = {};
    const float scale = rsqrtf((float)D_);

    for (int kj = 0; kj <= qi; kj++) {
        __syncthreads();   // prev-iter readers of KP/Vt done; also covers Qs on iter 0
        #pragma unroll
        for (int i = 0; i < 6; i++) {
            int idx = tid + i * 128;
            int r = idx / 12, c4 = (idx % 12) * 4;
            float4 kv = *(const float4*)&K[(size_t)(kj * 64 + r) * D_ + c4];
            float4 vv = *(const float4*)&V[(size_t)(kj * 64 + r) * D_ + c4];
            int pb = pbase4(c4);
            KP[r][pb+0] = to_tf32(kv.x); KP[r][pb+2] = to_tf32(kv.y);
            KP[r][pb+4] = to_tf32(kv.z); KP[r][pb+6] = to_tf32(kv.w);
            // V transposed: key r -> permuted column, d -> row
            int pk = (r & ~7) + 2*(r & 3) + ((r >> 2) & 1);
            Vt[c4+0][pk] = to_tf32(vv.x);
            Vt[c4+1][pk] = to_tf32(vv.y);
            Vt[c4+2][pk] = to_tf32(vv.z);
            Vt[c4+3][pk] = to_tf32(vv.w);
        }
        if (tid < 64) Ms[tid] = (1.0f - amask[b * T_ + kj * 64 + tid]) * -10000.0f;
        __syncthreads();

        // ---- S = Q K^T ----
        float s[8][4] = {};
        #pragma unroll
        for (int ks = 0; ks < 6; ks++) {
            const int ko = ks * 8 + 2 * tg;
            float2 q0 = *(const float2*)&Qs[w*16 + g    ][ko];
            float2 q1 = *(const float2*)&Qs[w*16 + g + 8][ko];
            float a[4] = {q0.x, q1.x, q0.y, q1.y};
            #pragma unroll
            for (int nf = 0; nf < 8; nf++) {
                float2 bb = *(const float2*)&KP[nf*8 + g][ko];
                mma_tf32(s[nf], a, &bb.x);
            }
        }

        // ---- scale + masks + online softmax ----
        const int qrow0 = qi * 64 + w * 16 + g;  // row for half=0; +8 for half=1
        float rmax[2];
        rmax[0] = -INFINITY; rmax[1] = -INFINITY;
        #pragma unroll
        for (int nf = 0; nf < 8; nf++) {
            int kc  = kj * 64 + nf * 8 + 2 * tg;
            float ma0 = Ms[nf * 8 + 2 * tg];
            float ma1 = Ms[nf * 8 + 2 * tg + 1];
            #pragma unroll
            for (int half = 0; half < 2; half++) {
                int qr = qrow0 + half * 8;
                float v0 = s[nf][2*half+0] * scale + ma0;
                float v1 = s[nf][2*half+1] * scale + ma1;
                v0 = (kc     > qr) ? -INFINITY : v0;
                v1 = (kc + 1 > qr) ? -INFINITY : v1;
                s[nf][2*half+0] = v0; s[nf][2*half+1] = v1;
                rmax[half] = fmaxf(rmax[half], fmaxf(v0, v1));
            }
        }
        #pragma unroll
        for (int off = 1; off <= 2; off <<= 1) {
            rmax[0] = fmaxf(rmax[0], __shfl_xor_sync(FULL, rmax[0], off));
            rmax[1] = fmaxf(rmax[1], __shfl_xor_sync(FULL, rmax[1], off));
        }

        float corr[2], rsum[2] = {0.f, 0.f};
        #pragma unroll
        for (int half = 0; half < 2; half++) {
            float mnew = fmaxf(m_i[half], rmax[half]);
            corr[half] = __expf(m_i[half] - mnew);   // exp(-inf)=0 on first block
            m_i[half] = mnew;
        }
        #pragma unroll
        for (int nf = 0; nf < 8; nf++) {
            #pragma unroll
            for (int half = 0; half < 2; half++) {
                float v0 = __expf(s[nf][2*half+0] - m_i[half]);
                float v1 = __expf(s[nf][2*half+1] - m_i[half]);
                rsum[half] += v0 + v1;
                s[nf][2*half+0] = to_tf32(v0);      // pre-round P for the PV mma
                s[nf][2*half+1] = to_tf32(v1);
            }
        }
        #pragma unroll
        for (int off = 1; off <= 2; off <<= 1) {
            rsum[0] += __shfl_xor_sync(FULL, rsum[0], off);
            rsum[1] += __shfl_xor_sync(FULL, rsum[1], off);
        }
        #pragma unroll
        for (int half = 0; half < 2; half++) {
            l_i[half] = l_i[half] * corr[half] + rsum[half];
        }
        #pragma unroll
        for (int nf = 0; nf < 6; nf++) {
            o[nf][0] *= corr[0]; o[nf][1] *= corr[0];
            o[nf][2] *= corr[1]; o[nf][3] *= corr[1];
        }

        // ---- O += P V : P A-fragments rebuilt via shuffles (no smem, no barrier) ----
        // P[w16+g][ks*8+c] lives in lane 4g+(c>>1), reg (c&1) (+2 for row +8).
        #pragma unroll
        for (int ks = 0; ks < 8; ks++) {
            int src0 = 4*g + (tg >> 1);        // column tg
            int src1 = src0 + 2;               // column tg+4
            float va0 = __shfl_sync(FULL, s[ks][0], src0);
            float va1 = __shfl_sync(FULL, s[ks][1], src0);
            float vb0 = __shfl_sync(FULL, s[ks][2], src0);
            float vb1 = __shfl_sync(FULL, s[ks][3], src0);
            float vc0 = __shfl_sync(FULL, s[ks][0], src1);
            float vc1 = __shfl_sync(FULL, s[ks][1], src1);
            float vd0 = __shfl_sync(FULL, s[ks][2], src1);
            float vd1 = __shfl_sync(FULL, s[ks][3], src1);
            bool odd = tg & 1;
            float a[4];
            a[0] = odd ? va1 : va0;            // P[g   ][tg]
            a[1] = odd ? vb1 : vb0;            // P[g+8 ][tg]
            a[2] = odd ? vc1 : vc0;            // P[g   ][tg+4]
            a[3] = odd ? vd1 : vd0;            // P[g+8 ][tg+4]
            const int ko = ks * 8 + 2 * tg;
            #pragma unroll
            for (int nf = 0; nf < 6; nf++) {
                float2 bb = *(const float2*)&Vt[nf*8 + g][ko];
                mma_tf32(o[nf], a, &bb.x);
            }
        }
    }

    // ---- normalize + write ctx [B,T,C] ----
    const int h = bh & 15;
    float invl[2] = {1.0f / l_i[0], 1.0f / l_i[1]};
    #pragma unroll
    for (int half = 0; half < 2; half++) {
        int t = qi * 64 + w * 16 + g + half * 8;
        size_t base = (size_t)(b * T_ + t) * C_ + h * D_;
        #pragma unroll
        for (int nf = 0; nf < 6; nf++) {
            int d = nf * 8 + 2 * tg;
            float2 v;
            v.x = o[nf][2*half+0] * invl[half];
            v.y = o[nf][2*half+1] * invl[half];
            *(float2*)&g_ctx[base + d] = v;
        }
    }
}

// ---------------- output projection: out = ctx @ Wo^T + bo (tf32 mma) -----------
// grid: (BT/64, C/64)  block: 128. Tile 64x64, K-chunk 32, pitch 40.
__global__ __launch_bounds__(128) void out_proj_kernel(
    const float* __restrict__ Wo, const float* __restrict__ bo,
    float* __restrict__ out)
{
    const int mt = blockIdx.x, nt = blockIdx.y;
    __shared__ float As[64][40];
    __shared__ float Bs[64][40];

    const int tid  = threadIdx.x;
    const int lane = tid & 31;
    const int w    = tid >> 5;
    const int g    = lane >> 2;
    const int tg   = lane & 3;
    const int row0 = mt * 64, col0 = nt * 64;

    float acc[8][4] = {};

    for (int k0 = 0; k0 < C_; k0 += 32) {
        #pragma unroll
        for (int i = 0; i < 4; i++) {
            int idx = tid + i * 128;
            int r = idx >> 3, c4 = (idx & 7) * 4;
            float4 va = *(const float4*)&g_ctx[(size_t)(row0 + r) * C_ + k0 + c4];
            float4 vb = *(const float4*)&Wo  [(size_t)(col0 + r) * C_ + k0 + c4];
            int pb = pbase4(c4);
            As[r][pb+0] = to_tf32(va.x); As[r][pb+2] = to_tf32(va.y);
            As[r][pb+4] = to_tf32(va.z); As[r][pb+6] = to_tf32(va.w);
            Bs[r][pb+0] = to_tf32(vb.x); Bs[r][pb+2] = to_tf32(vb.y);
            Bs[r][pb+4] = to_tf32(vb.z); Bs[r][pb+6] = to_tf32(vb.w);
        }
        __syncthreads();
        #pragma unroll
        for (int ks = 0; ks < 4; ks++) {
            const int ko = ks * 8 + 2 * tg;
            float2 a0 = *(const float2*)&As[w*16 + g    ][ko];
            float2 a1 = *(const float2*)&As[w*16 + g + 8][ko];
            float a[4] = {a0.x, a1.x, a0.y, a1.y};
            #pragma unroll
            for (int nf = 0; nf < 8; nf++) {
                float2 bb = *(const float2*)&Bs[nf*8 + g][ko];
                mma_tf32(acc[nf], a, &bb.x);
            }
        }
        __syncthreads();
    }

    #pragma unroll
    for (int half = 0; half < 2; half++) {
        int r = row0 + w * 16 + g + half * 8;
        #pragma unroll
        for (int nf = 0; nf < 8; nf++) {
            int c = col0 + nf * 8 + 2 * tg;
            float2 v;
            v.x = acc[nf][2*half+0] + bo[c];
            v.y = acc[nf][2*half+1] + bo[c + 1];
            *(float2*)&out[(size_t)r * C_ + c] = v;
        }
    }
}

// ---------------- launch -------------------------------------------------------
extern "C" void kernel_launch(void* const* d_in, const int* in_sizes, int n_in,
                              void* d_out, int out_size)
{
    const float* X     = (const float*)d_in[0];
    const float* amask = (const float*)d_in[1];
    const float* Wq    = (const float*)d_in[2];
    const float* bq    = (const float*)d_in[3];
    const float* Wk    = (const float*)d_in[4];
    const float* bk    = (const float*)d_in[5];
    const float* Wv    = (const float*)d_in[6];
    const float* bv    = (const float*)d_in[7];
    const float* Wo    = (const float*)d_in[8];
    const float* bo    = (const float*)d_in[9];
    float* out = (float*)d_out;

    rope_table_kernel<<<(T_ * D_ + 255) / 256, 256>>>();
    qkv_proj_kernel<<<dim3((B_ * T_) / 64, H_, 3), 128>>>(X, Wq, bq, Wk, bk, Wv, bv);
    attn_kernel<<<dim3(T_ / 64, B_ * H_), 128>>>(amask);
    out_proj_kernel<<<dim3((B_ * T_) / 64, C_ / 64), 128>>>(Wo, bo, out);
}

// round 6
// speedup vs baseline: 1.5075x; 1.5075x over previous
#include <cuda_runtime.h>
#include <math.h>
#include <stdint.h>

#define B_ 4
#define T_ 2048
#define C_ 768
#define H_ 16
#define D_ 48

// ---------------- scratch (static device globals; no allocation) ----------------
__device__ float g_qh[B_*H_*T_*D_];   // Q, roped, [B,H,T,D]
__device__ float g_kh[B_*H_*T_*D_];   // K, roped, [B,H,T,D]
__device__ float g_vh[B_*H_*T_*D_];   // V,        [B,H,T,D]
__device__ float g_ctx[B_*T_*C_];     // attention output, [B,T,C]
__device__ float g_cos[T_*D_];
__device__ float g_sin[T_*D_];

// ---------------- helpers -------------------------------------------------------
__device__ __forceinline__ float to_tf32(float x) {
    uint32_t u;
    asm("cvt.rna.tf32.f32 %0, %1;" : "=r"(u) : "f"(x));
    return __uint_as_float(u);
}

// d += a * b   (m16n8k8, tf32 inputs as f32 bit patterns, f32 accum)
__device__ __forceinline__ void mma_tf32(float* d, const float* a, const float* b) {
    asm volatile(
        "mma.sync.aligned.m16n8k8.row.col.f32.tf32.tf32.f32 "
        "{%0,%1,%2,%3}, {%4,%5,%6,%7}, {%8,%9}, {%0,%1,%2,%3};\n"
        : "+f"(d[0]), "+f"(d[1]), "+f"(d[2]), "+f"(d[3])
        : "r"(__float_as_uint(a[0])), "r"(__float_as_uint(a[1])),
          "r"(__float_as_uint(a[2])), "r"(__float_as_uint(a[3])),
          "r"(__float_as_uint(b[0])), "r"(__float_as_uint(b[1])));
}

// ---------------- RoPE table (fp64 for accuracy) --------------------------------
__global__ void rope_table_kernel() {
    int i = blockIdx.x * blockDim.x + threadIdx.x;
    if (i >= T_ * D_) return;
    int t = i / D_, d = i % D_;
    int p = (d < D_/2) ? d : d - D_/2;
    double inv = exp(-(2.0 * p / (double)D_) * log(10000.0));
    double ang = (double)t * inv;
    g_cos[i] = (float)cos(ang);
    g_sin[i] = (float)sin(ang);
}

// ---------------- fused QKV projection + bias + RoPE (tf32 mma) -----------------
// grid: (BT/64, H, 3)  block: 128 (4 warps). Tile: 64 x 48 (one head), K-chunk 32.
// Software-pipelined: next k-chunk prefetched into registers during compute.
__global__ __launch_bounds__(128) void qkv_proj_kernel(
    const float* __restrict__ X,
    const float* __restrict__ Wq, const float* __restrict__ bq,
    const float* __restrict__ Wk, const float* __restrict__ bk,
    const float* __restrict__ Wv, const float* __restrict__ bv)
{
    const int mt = blockIdx.x, h = blockIdx.y, which = blockIdx.z;
    const float* W    = (which == 0) ? Wq : ((which == 1) ? Wk : Wv);
    const float* bias = (which == 0) ? bq : ((which == 1) ? bk : bv);
    float* out        = (which == 0) ? g_qh : ((which == 1) ? g_kh : g_vh);

    __shared__ float As[64][36];   // X tile (tf32-rounded), stride 36 -> conflict-free frags
    __shared__ float Bs[48][36];   // W tile

    const int tid  = threadIdx.x;
    const int lane = tid & 31;
    const int w    = tid >> 5;
    const int row0 = mt * 64, col0 = h * 48;
    const int g    = lane >> 2;
    const int tg   = lane & 3;

    // per-thread load coordinates
    const int ar_ = tid >> 3, ac_ = (tid & 7) * 4;   // A: 4 rows apart stride 32... (idx pattern below)
    float4 xa[4], wb[3];

    // prefetch chunk 0
    #pragma unroll
    for (int i = 0; i < 4; i++) {
        int idx = tid + i * 128;
        int r = idx >> 3, c4 = (idx & 7) * 4;
        xa[i] = *(const float4*)&X[(size_t)(row0 + r) * C_ + c4];
    }
    #pragma unroll
    for (int i = 0; i < 3; i++) {
        int idx = tid + i * 128;
        int r = idx >> 3, c4 = (idx & 7) * 4;
        wb[i] = *(const float4*)&W[(size_t)(col0 + r) * C_ + c4];
    }

    float acc[6][4] = {};

    for (int k0 = 0; k0 < C_; k0 += 32) {
        __syncthreads();   // previous compute readers done (no-op on iter 0)
        #pragma unroll
        for (int i = 0; i < 4; i++) {
            int idx = tid + i * 128;
            int r = idx >> 3, c4 = (idx & 7) * 4;
            As[r][c4+0] = to_tf32(xa[i].x); As[r][c4+1] = to_tf32(xa[i].y);
            As[r][c4+2] = to_tf32(xa[i].z); As[r][c4+3] = to_tf32(xa[i].w);
        }
        #pragma unroll
        for (int i = 0; i < 3; i++) {
            int idx = tid + i * 128;
            int r = idx >> 3, c4 = (idx & 7) * 4;
            Bs[r][c4+0] = to_tf32(wb[i].x); Bs[r][c4+1] = to_tf32(wb[i].y);
            Bs[r][c4+2] = to_tf32(wb[i].z); Bs[r][c4+3] = to_tf32(wb[i].w);
        }
        // prefetch next chunk (overlaps with mma below)
        if (k0 + 32 < C_) {
            #pragma unroll
            for (int i = 0; i < 4; i++) {
                int idx = tid + i * 128;
                int r = idx >> 3, c4 = (idx & 7) * 4;
                xa[i] = *(const float4*)&X[(size_t)(row0 + r) * C_ + k0 + 32 + c4];
            }
            #pragma unroll
            for (int i = 0; i < 3; i++) {
                int idx = tid + i * 128;
                int r = idx >> 3, c4 = (idx & 7) * 4;
                wb[i] = *(const float4*)&W[(size_t)(col0 + r) * C_ + k0 + 32 + c4];
            }
        }
        __syncthreads();
        #pragma unroll
        for (int ks = 0; ks < 4; ks++) {
            float a[4];
            int ar = w * 16 + g, ac = ks * 8 + tg;
            a[0] = As[ar][ac];     a[1] = As[ar+8][ac];
            a[2] = As[ar][ac+4];   a[3] = As[ar+8][ac+4];
            #pragma unroll
            for (int nf = 0; nf < 6; nf++) {
                float bf[2];
                int br = nf * 8 + g, bc = ks * 8 + tg;
                bf[0] = Bs[br][bc]; bf[1] = Bs[br][bc+4];
                mma_tf32(acc[nf], a, bf);
            }
        }
    }

    // epilogue: bias + RoPE fully in registers (pair d <-> d+24 == frag nf <-> nf+3)
    #pragma unroll
    for (int half = 0; half < 2; half++) {
        int grow = row0 + w * 16 + g + half * 8;
        int b = grow >> 11;             // T_ = 2048
        int t = grow & (T_ - 1);
        size_t base = ((size_t)((b * H_ + h) * T_) + t) * D_;
        if (which == 2) {
            #pragma unroll
            for (int nf = 0; nf < 6; nf++) {
                int d = nf * 8 + 2 * tg;
                float2 v;
                v.x = acc[nf][2*half+0] + bias[col0 + d];
                v.y = acc[nf][2*half+1] + bias[col0 + d + 1];
                *(float2*)&out[base + d] = v;
            }
        } else {
            #pragma unroll
            for (int nf = 0; nf < 3; nf++) {
                int d = nf * 8 + 2 * tg;
                float c0 = g_cos[t * D_ + d],     s0 = g_sin[t * D_ + d];
                float c1 = g_cos[t * D_ + d + 1], s1 = g_sin[t * D_ + d + 1];
                float x1a = acc[nf  ][2*half+0] + bias[col0 + d];
                float x1b = acc[nf  ][2*half+1] + bias[col0 + d + 1];
                float x2a = acc[nf+3][2*half+0] + bias[col0 + d + 24];
                float x2b = acc[nf+3][2*half+1] + bias[col0 + d + 25];
                float2 lo, hi;
                lo.x = x1a * c0 - x2a * s0;  lo.y = x1b * c1 - x2b * s1;
                hi.x = x2a * c0 + x1a * s0;  hi.y = x2b * c1 + x1b * s1;
                *(float2*)&out[base + d]      = lo;
                *(float2*)&out[base + d + 24] = hi;
            }
        }
    }
}

// ---------------- flash-style causal attention (tf32 mma) -----------------------
// grid: (T/64, B*H)  block: 128 (4 warps). S tile 64x64, D=48 resident.
// KP stride 68: K tile (48 cols) then P tile (64 cols); conflict-free (68 mod 32 = 4).
// Software-pipelined: next key block's K/V prefetched into registers during compute.
__global__ __launch_bounds__(128) void attn_kernel(const float* __restrict__ amask)
{
    const int qi = gridDim.x - 1 - blockIdx.x;
    const int bh = blockIdx.y;
    const int b = bh >> 4;
    const float* Q = g_qh + (size_t)bh * T_ * D_;
    const float* K = g_kh + (size_t)bh * T_ * D_;
    const float* V = g_vh + (size_t)bh * T_ * D_;

    __shared__ float Qs[64][52];   // stride 52 -> conflict-free A frag loads
    __shared__ float KP[64][68];   // K tile (48 cols) / P tile (64 cols)
    __shared__ float Vs[64][56];   // stride 56 -> conflict-free B frag loads
    __shared__ float Ms[64];       // additive padding mask for current key block

    const int tid  = threadIdx.x;
    const int lane = tid & 31;
    const int w    = tid >> 5;
    const int g    = lane >> 2;
    const int tg   = lane & 3;

    #pragma unroll
    for (int i = 0; i < 6; i++) {            // 64x48 = 768 float4
        int idx = tid + i * 128;
        int r = idx / 12, c4 = (idx % 12) * 4;
        float4 v = *(const float4*)&Q[(size_t)(qi * 64 + r) * D_ + c4];
        Qs[r][c4+0] = to_tf32(v.x); Qs[r][c4+1] = to_tf32(v.y);
        Qs[r][c4+2] = to_tf32(v.z); Qs[r][c4+3] = to_tf32(v.w);
    }

    // prefetch key block 0
    float4 kr[6], vr[6];
    float  msr;
    #pragma unroll
    for (int i = 0; i < 6; i++) {
        int idx = tid + i * 128;
        int r = idx / 12, c4 = (idx % 12) * 4;
        kr[i] = *(const float4*)&K[(size_t)r * D_ + c4];
        vr[i] = *(const float4*)&V[(size_t)r * D_ + c4];
    }
    msr = (tid < 64) ? amask[b * T_ + tid] : 0.f;

    float m_i[2], l_i[2] = {0.f, 0.f};
    m_i[0] = -INFINITY; m_i[1] = -INFINITY;
    float o[6][4] = {};
    const float scale = rsqrtf((float)D_);

    for (int kj = 0; kj <= qi; kj++) {
        __syncthreads();   // prev-iter readers of KP/Vs done; also covers Qs on iter 0
        #pragma unroll
        for (int i = 0; i < 6; i++) {
            int idx = tid + i * 128;
            int r = idx / 12, c4 = (idx % 12) * 4;
            KP[r][c4+0] = to_tf32(kr[i].x); KP[r][c4+1] = to_tf32(kr[i].y);
            KP[r][c4+2] = to_tf32(kr[i].z); KP[r][c4+3] = to_tf32(kr[i].w);
            Vs[r][c4+0] = to_tf32(vr[i].x); Vs[r][c4+1] = to_tf32(vr[i].y);
            Vs[r][c4+2] = to_tf32(vr[i].z); Vs[r][c4+3] = to_tf32(vr[i].w);
        }
        if (tid < 64) Ms[tid] = (1.0f - msr) * -10000.0f;
        // prefetch next key block (latency hidden behind mma + softmax below)
        if (kj < qi) {
            #pragma unroll
            for (int i = 0; i < 6; i++) {
                int idx = tid + i * 128;
                int r = idx / 12, c4 = (idx % 12) * 4;
                kr[i] = *(const float4*)&K[(size_t)((kj+1) * 64 + r) * D_ + c4];
                vr[i] = *(const float4*)&V[(size_t)((kj+1) * 64 + r) * D_ + c4];
            }
            if (tid < 64) msr = amask[b * T_ + (kj+1) * 64 + tid];
        }
        __syncthreads();

        // ---- S = Q K^T ----
        float s[8][4] = {};
        #pragma unroll
        for (int ks = 0; ks < 6; ks++) {
            float a[4];
            int ar = w * 16 + g, ac = ks * 8 + tg;
            a[0] = Qs[ar][ac];   a[1] = Qs[ar+8][ac];
            a[2] = Qs[ar][ac+4]; a[3] = Qs[ar+8][ac+4];
            #pragma unroll
            for (int nf = 0; nf < 8; nf++) {
                float bf[2];
                int br = nf * 8 + g, bc = ks * 8 + tg;
                bf[0] = KP[br][bc]; bf[1] = KP[br][bc+4];
                mma_tf32(s[nf], a, bf);
            }
        }

        // ---- scale + masks + online softmax ----
        const int qrow0 = qi * 64 + w * 16 + g;  // row for half=0; +8 for half=1
        float rmax[2];
        rmax[0] = -INFINITY; rmax[1] = -INFINITY;
        #pragma unroll
        for (int nf = 0; nf < 8; nf++) {
            int kc  = kj * 64 + nf * 8 + 2 * tg;
            float ma0 = Ms[nf * 8 + 2 * tg];
            float ma1 = Ms[nf * 8 + 2 * tg + 1];
            #pragma unroll
            for (int half = 0; half < 2; half++) {
                int qr = qrow0 + half * 8;
                float v0 = s[nf][2*half+0] * scale + ma0;
                float v1 = s[nf][2*half+1] * scale + ma1;
                v0 = (kc     > qr) ? -INFINITY : v0;
                v1 = (kc + 1 > qr) ? -INFINITY : v1;
                s[nf][2*half+0] = v0; s[nf][2*half+1] = v1;
                rmax[half] = fmaxf(rmax[half], fmaxf(v0, v1));
            }
        }
        #pragma unroll
        for (int off = 1; off <= 2; off <<= 1) {
            rmax[0] = fmaxf(rmax[0], __shfl_xor_sync(0xffffffffu, rmax[0], off));
            rmax[1] = fmaxf(rmax[1], __shfl_xor_sync(0xffffffffu, rmax[1], off));
        }

        float corr[2], rsum[2] = {0.f, 0.f};
        #pragma unroll
        for (int half = 0; half < 2; half++) {
            float mnew = fmaxf(m_i[half], rmax[half]);
            corr[half] = __expf(m_i[half] - mnew);   // exp(-inf)=0 on first block
            m_i[half] = mnew;
        }
        #pragma unroll
        for (int nf = 0; nf < 8; nf++) {
            #pragma unroll
            for (int half = 0; half < 2; half++) {
                float v0 = __expf(s[nf][2*half+0] - m_i[half]);
                float v1 = __expf(s[nf][2*half+1] - m_i[half]);
                s[nf][2*half+0] = v0; s[nf][2*half+1] = v1;
                rsum[half] += v0 + v1;
            }
        }
        #pragma unroll
        for (int off = 1; off <= 2; off <<= 1) {
            rsum[0] += __shfl_xor_sync(0xffffffffu, rsum[0], off);
            rsum[1] += __shfl_xor_sync(0xffffffffu, rsum[1], off);
        }
        #pragma unroll
        for (int half = 0; half < 2; half++) {
            l_i[half] = l_i[half] * corr[half] + rsum[half];
        }
        #pragma unroll
        for (int nf = 0; nf < 6; nf++) {
            o[nf][0] *= corr[0]; o[nf][1] *= corr[0];
            o[nf][2] *= corr[1]; o[nf][3] *= corr[1];
        }

        // ---- P -> KP (all S-mma reads of KP are complete) ----
        __syncthreads();
        {
            int pr = w * 16 + g;
            #pragma unroll
            for (int nf = 0; nf < 8; nf++) {
                int pc = nf * 8 + 2 * tg;
                float2 lo, hi;
                lo.x = to_tf32(s[nf][0]); lo.y = to_tf32(s[nf][1]);
                hi.x = to_tf32(s[nf][2]); hi.y = to_tf32(s[nf][3]);
                *(float2*)&KP[pr    ][pc] = lo;
                *(float2*)&KP[pr + 8][pc] = hi;
            }
        }
        __syncthreads();

        // ---- O += P V ----
        #pragma unroll
        for (int ks = 0; ks < 8; ks++) {
            float a[4];
            int ar = w * 16 + g, ac = ks * 8 + tg;
            a[0] = KP[ar][ac];   a[1] = KP[ar+8][ac];
            a[2] = KP[ar][ac+4]; a[3] = KP[ar+8][ac+4];
            #pragma unroll
            for (int nf = 0; nf < 6; nf++) {
                float bf[2];
                int vrr = ks * 8 + tg, vc = nf * 8 + g;
                bf[0] = Vs[vrr][vc]; bf[1] = Vs[vrr + 4][vc];
                mma_tf32(o[nf], a, bf);
            }
        }
    }

    // ---- normalize + write ctx [B,T,C] ----
    const int h = bh & 15;
    float invl[2] = {1.0f / l_i[0], 1.0f / l_i[1]};
    #pragma unroll
    for (int half = 0; half < 2; half++) {
        int t = qi * 64 + w * 16 + g + half * 8;
        size_t base = (size_t)(b * T_ + t) * C_ + h * D_;
        #pragma unroll
        for (int nf = 0; nf < 6; nf++) {
            int d = nf * 8 + 2 * tg;
            float2 v;
            v.x = o[nf][2*half+0] * invl[half];
            v.y = o[nf][2*half+1] * invl[half];
            *(float2*)&g_ctx[base + d] = v;
        }
    }
}

// ---------------- output projection: out = ctx @ Wo^T + bo (tf32 mma) -----------
// grid: (BT/64, C/64)  block: 128. Tile 64x64, K-chunk 32. Pipelined prefetch.
__global__ __launch_bounds__(128) void out_proj_kernel(
    const float* __restrict__ Wo, const float* __restrict__ bo,
    float* __restrict__ out)
{
    const int mt = blockIdx.x, nt = blockIdx.y;
    __shared__ float As[64][36];
    __shared__ float Bs[64][36];

    const int tid  = threadIdx.x;
    const int lane = tid & 31;
    const int w    = tid >> 5;
    const int g    = lane >> 2;
    const int tg   = lane & 3;
    const int row0 = mt * 64, col0 = nt * 64;

    float4 ca[4], wb[4];
    #pragma unroll
    for (int i = 0; i < 4; i++) {
        int idx = tid + i * 128;
        int r = idx >> 3, c4 = (idx & 7) * 4;
        ca[i] = *(const float4*)&g_ctx[(size_t)(row0 + r) * C_ + c4];
        wb[i] = *(const float4*)&Wo  [(size_t)(col0 + r) * C_ + c4];
    }

    float acc[8][4] = {};

    for (int k0 = 0; k0 < C_; k0 += 32) {
        __syncthreads();
        #pragma unroll
        for (int i = 0; i < 4; i++) {
            int idx = tid + i * 128;
            int r = idx >> 3, c4 = (idx & 7) * 4;
            As[r][c4+0] = to_tf32(ca[i].x); As[r][c4+1] = to_tf32(ca[i].y);
            As[r][c4+2] = to_tf32(ca[i].z); As[r][c4+3] = to_tf32(ca[i].w);
            Bs[r][c4+0] = to_tf32(wb[i].x); Bs[r][c4+1] = to_tf32(wb[i].y);
            Bs[r][c4+2] = to_tf32(wb[i].z); Bs[r][c4+3] = to_tf32(wb[i].w);
        }
        if (k0 + 32 < C_) {
            #pragma unroll
            for (int i = 0; i < 4; i++) {
                int idx = tid + i * 128;
                int r = idx >> 3, c4 = (idx & 7) * 4;
                ca[i] = *(const float4*)&g_ctx[(size_t)(row0 + r) * C_ + k0 + 32 + c4];
                wb[i] = *(const float4*)&Wo  [(size_t)(col0 + r) * C_ + k0 + 32 + c4];
            }
        }
        __syncthreads();
        #pragma unroll
        for (int ks = 0; ks < 4; ks++) {
            float a[4];
            int ar = w * 16 + g, ac = ks * 8 + tg;
            a[0] = As[ar][ac];   a[1] = As[ar+8][ac];
            a[2] = As[ar][ac+4]; a[3] = As[ar+8][ac+4];
            #pragma unroll
            for (int nf = 0; nf < 8; nf++) {
                float bf[2];
                int br = nf * 8 + g, bc = ks * 8 + tg;
                bf[0] = Bs[br][bc]; bf[1] = Bs[br][bc+4];
                mma_tf32(acc[nf], a, bf);
            }
        }
    }

    #pragma unroll
    for (int half = 0; half < 2; half++) {
        int r = row0 + w * 16 + g + half * 8;
        #pragma unroll
        for (int nf = 0; nf < 8; nf++) {
            int c = col0 + nf * 8 + 2 * tg;
            float2 v;
            v.x = acc[nf][2*half+0] + bo[c];
            v.y = acc[nf][2*half+1] + bo[c + 1];
            *(float2*)&out[(size_t)r * C_ + c] = v;
        }
    }
}

// ---------------- launch -------------------------------------------------------
extern "C" void kernel_launch(void* const* d_in, const int* in_sizes, int n_in,
                              void* d_out, int out_size)
{
    const float* X     = (const float*)d_in[0];
    const float* amask = (const float*)d_in[1];
    const float* Wq    = (const float*)d_in[2];
    const float* bq    = (const float*)d_in[3];
    const float* Wk    = (const float*)d_in[4];
    const float* bk    = (const float*)d_in[5];
    const float* Wv    = (const float*)d_in[6];
    const float* bv    = (const float*)d_in[7];
    const float* Wo    = (const float*)d_in[8];
    const float* bo    = (const float*)d_in[9];
    float* out = (float*)d_out;

    rope_table_kernel<<<(T_ * D_ + 255) / 256, 256>>>();
    qkv_proj_kernel<<<dim3((B_ * T_) / 64, H_, 3), 128>>>(X, Wq, bq, Wk, bk, Wv, bv);
    attn_kernel<<<dim3(T_ / 64, B_ * H_), 128>>>(amask);
    out_proj_kernel<<<dim3((B_ * T_) / 64, C_ / 64), 128>>>(Wo, bo, out);
}